// round 7
// baseline (speedup 1.0000x reference)
#include <cuda_runtime.h>
#include <cuda_fp16.h>
#include <math.h>
#include <stdint.h>
#include <string.h>

// Problem constants
#define NG   16
#define NIX  32
#define NIZ  32
#define NOUT 64
#define NB   512
#define NC   17
#define IJ   (NIX * NIZ)          // 1024
#define NBLK 148                  // persistent blocks (1/SM)
#define MAXT 7                    // max ij's per block: ceil(1024/148)
#define SLAB_HALFS (NC * NC * NOUT)   // 289*64 = 18496
#define SLAB_BYTES (SLAB_HALFS * 2)   // 36992
#define SLAB_CHUNKS (SLAB_BYTES / 16) // 2312
#define OUTE (NOUT * NB)              // 32768

// Repacked parameter tensor in fp16: P2h[cell][ij][o]  (o contiguous)
__device__ __half g_P2h[NC * NC * IJ * NOUT];
// Per-block partial outputs: 148 x 64 x 512 f32 = 19.4 MB
__device__ float g_part[NBLK * OUTE];

// ---------------------------------------------------------------------------
// Repack: P[ii][jj][o][ij] (fp32) -> P2h[cell][ij][o] (fp16). (round-4 proven)
// ---------------------------------------------------------------------------
__global__ __launch_bounds__(256) void repack_kernel(const float* __restrict__ P) {
    __shared__ float tile[32][33];
    const int cell = blockIdx.z;
    const int o0   = blockIdx.y << 5;
    const int ij0  = blockIdx.x << 5;
    const float* src = P      + cell * (NOUT * IJ);
    __half*      dst = g_P2h  + cell * (IJ * NOUT);
    const int tx = threadIdx.x;
    const int ty = threadIdx.y;
#pragma unroll
    for (int r = 0; r < 32; r += 8)
        tile[ty + r][tx] = src[(o0 + ty + r) * IJ + (ij0 + tx)];
    __syncthreads();
#pragma unroll
    for (int r = 0; r < 32; r += 8)
        dst[(ij0 + ty + r) * NOUT + (o0 + tx)] = __float2half_rn(tile[tx][ty + r]);
}

// ---------------------------------------------------------------------------
// cp.async helpers
// ---------------------------------------------------------------------------
__device__ __forceinline__ uint32_t smem_u32(const void* p) {
    return (uint32_t)__cvta_generic_to_shared(p);
}
__device__ __forceinline__ void cp_async16(uint32_t saddr, const void* gptr) {
    asm volatile("cp.async.cg.shared.global [%0], [%1], 16;\n"
                 :: "r"(saddr), "l"(gptr) : "memory");
}
__device__ __forceinline__ void cp_commit() {
    asm volatile("cp.async.commit_group;\n" ::: "memory");
}
template <int N>
__device__ __forceinline__ void cp_wait() {
    asm volatile("cp.async.wait_group %0;\n" :: "n"(N) : "memory");
}

__device__ __forceinline__ unsigned h2u(__half2 h) {
    return *reinterpret_cast<unsigned*>(&h);
}

// Issue the 37 KB slab for one ij into smem stage buffer.
__device__ __forceinline__ void issue_slab(char* dsm, int stage, int ij, int tid) {
    const uint32_t sbase = smem_u32(dsm) + stage * SLAB_BYTES;
    for (int c = tid; c < SLAB_CHUNKS; c += 512) {
        const int line = c >> 3;            // cell 0..288
        const int sub  = c & 7;             // 16B sub-chunk within 128B row
        const __half* g = g_P2h + ((line * IJ + ij) * NOUT + sub * 8);
        cp_async16(sbase + c * 16, g);
    }
}

// Dynamic smem layout:
//   [0, 2*SLAB_BYTES)                          double-buffered slab (fp16)
//   [CELL_OFF, CELL_OFF + MAXT*512*4)          s_cell: local cell base (halfs)
//   [W_OFF,    W_OFF    + MAXT*512*16)         s_w: 4 duplicated-half2 weights
// Epilogue reuses the whole region as float out[64][512] (128 KB).
#define CELL_OFF (2 * SLAB_BYTES)                       // 73984
#define W_OFF    (CELL_OFF + MAXT * NB * 4)             // 88320
#define SMEM_MAIN (W_OFF + MAXT * NB * 16)              // 145664

// ---------------------------------------------------------------------------
// Cell-major gather: grid 148 persistent blocks; block handles ij = blk+148t.
// Each block accumulates a FULL out[64,512] partial in registers
// (thread = (bgrp, og) owns 8 batches x 8 o-elems).
// ---------------------------------------------------------------------------
__global__ __launch_bounds__(512, 1) void gather_kernel(
    const float* __restrict__ x,
    const float* __restrict__ z,
    const float* __restrict__ borders,
    const float* __restrict__ invlen)
{
    extern __shared__ char dsm[];
    const int blk = blockIdx.x;
    const int tid = threadIdx.x;
    const int nt  = (IJ - blk + NBLK - 1) / NBLK;   // 6 or 7 ij's

    int*   s_cell = reinterpret_cast<int*>(dsm + CELL_OFF);
    uint4* s_w    = reinterpret_cast<uint4*>(dsm + W_OFF);

    // Kick off slab 0 ASAP (independent of the meta prologue).
    issue_slab(dsm, 0, blk, tid);
    cp_commit();

    // Meta prologue: bins + weights for all of this block's ij's. tid == b.
    for (int t = 0; t < nt; ++t) {
        const int ij = blk + t * NBLK;
        const int i = ij >> 5;
        const int j = ij & 31;
        const float xv = x[i * NB + tid];
        const float zv = z[j * NB + tid];

        const float ex = expf(-fabsf(xv));
        const float cx = (xv > 0.0f) ? (1.0f - 0.5f * ex) : (0.5f * ex);
        int bx = (int)(cx * (float)NG); bx = max(0, min(NG - 1, bx));
        const float fx = (xv - borders[bx]) * invlen[bx];

        const float ez = expf(-fabsf(zv));
        const float cz = (zv > 0.0f) ? (1.0f - 0.5f * ez) : (0.5f * ez);
        int bz = (int)(cz * (float)NG); bz = max(0, min(NG - 1, bz));
        const float fz = (zv - borders[bz]) * invlen[bz];

        const float ax = 1.0f - fx;
        const float az = 1.0f - fz;
        uint4 wp;
        wp.x = h2u(__float2half2_rn(ax * az));
        wp.y = h2u(__float2half2_rn(ax * fz));
        wp.z = h2u(__float2half2_rn(fx * az));
        wp.w = h2u(__float2half2_rn(fx * fz));
        s_w[t * NB + tid]    = wp;
        s_cell[t * NB + tid] = (bx * NC + bz) * NOUT;   // local slab offset (halfs)
    }

    const int og   = tid & 7;       // o-group: halfs [og*8, og*8+8)
    const int bgrp = tid >> 3;      // 0..63; owns batches bgrp + 64k
    const int obyte = og * 16;      // byte offset within a 128B row

    float acc[8][8];
#pragma unroll
    for (int k = 0; k < 8; ++k)
#pragma unroll
        for (int e = 0; e < 8; ++e) acc[k][e] = 0.0f;

    for (int t = 0; t < nt; ++t) {
        if (t + 1 < nt) {                     // prefetch next slab
            issue_slab(dsm, (t + 1) & 1, blk + (t + 1) * NBLK, tid);
            cp_commit();
            cp_wait<1>();                     // slab t complete
        } else {
            cp_wait<0>();
        }
        __syncthreads();

        const char* slab = dsm + (t & 1) * SLAB_BYTES;
        const int*   cellp = s_cell + t * NB;
        const uint4* wpp   = s_w    + t * NB;

#pragma unroll
        for (int k = 0; k < 8; ++k) {
            const int b  = bgrp + (k << 6);
            const int cb = cellp[b];          // LDS broadcast (4 addrs/warp)
            const uint4 wq = wpp[b];          // LDS.128 broadcast
            const __half2 w00 = *reinterpret_cast<const __half2*>(&wq.x);
            const __half2 w01 = *reinterpret_cast<const __half2*>(&wq.y);
            const __half2 w10 = *reinterpret_cast<const __half2*>(&wq.z);
            const __half2 w11 = *reinterpret_cast<const __half2*>(&wq.w);

            const char* p = slab + cb * 2 + obyte;
            const uint4 q00 = *reinterpret_cast<const uint4*>(p);
            const uint4 q01 = *reinterpret_cast<const uint4*>(p + NOUT * 2);            // bz+1
            const uint4 q10 = *reinterpret_cast<const uint4*>(p + NC * NOUT * 2);       // bx+1
            const uint4 q11 = *reinterpret_cast<const uint4*>(p + (NC + 1) * NOUT * 2); // both

            const __half2* h00 = reinterpret_cast<const __half2*>(&q00);
            const __half2* h01 = reinterpret_cast<const __half2*>(&q01);
            const __half2* h10 = reinterpret_cast<const __half2*>(&q10);
            const __half2* h11 = reinterpret_cast<const __half2*>(&q11);
#pragma unroll
            for (int m = 0; m < 4; ++m) {
                __half2 tm = __hmul2(h00[m], w00);       // chain length 4
                tm = __hfma2(h01[m], w01, tm);
                tm = __hfma2(h10[m], w10, tm);
                tm = __hfma2(h11[m], w11, tm);
                const float2 f = __half22float2(tm);     // per-cell f32 flush
                acc[k][2 * m + 0] += f.x;
                acc[k][2 * m + 1] += f.y;
            }
        }
        __syncthreads();   // protect stage buffer before t+2's prefetch
    }

    // Epilogue: stage partial in smem (reuse whole region), then linear copy.
    float* s_out = reinterpret_cast<float*>(dsm);
#pragma unroll
    for (int k = 0; k < 8; ++k)
#pragma unroll
        for (int e = 0; e < 8; ++e)
            s_out[(og * 8 + e) * NB + bgrp + (k << 6)] = acc[k][e];
    __syncthreads();

    float4*       dst = reinterpret_cast<float4*>(g_part + blk * OUTE);
    const float4* src = reinterpret_cast<const float4*>(s_out);
#pragma unroll
    for (int c = tid; c < OUTE / 4; c += 512)
        dst[c] = src[c];
}

// ---------------------------------------------------------------------------
// Reduce: out[e] = sum over 148 partials. 19.4 MB read.
// ---------------------------------------------------------------------------
__global__ __launch_bounds__(256) void reduce_kernel(float* __restrict__ out) {
    const int e = blockIdx.x * 256 + threadIdx.x;   // 0..32767
    float a = 0.0f;
#pragma unroll 4
    for (int s = 0; s < NBLK; ++s)
        a += g_part[s * OUTE + e];
    out[e] = a;
}

// ---------------------------------------------------------------------------
extern "C" void kernel_launch(void* const* d_in, const int* in_sizes, int n_in,
                              void* d_out, int out_size) {
    const float* x       = (const float*)d_in[0];  // (32, 512)
    const float* z       = (const float*)d_in[1];  // (32, 512)
    const float* P       = (const float*)d_in[2];  // (17,17,64,32,32)
    const float* borders = (const float*)d_in[3];  // (17,)
    const float* invlen  = (const float*)d_in[4];  // (16,)
    float* out = (float*)d_out;                    // (64, 512)

    (void)in_sizes; (void)n_in; (void)out_size;

    static int smem_set = 0;
    if (!smem_set) {
        cudaFuncSetAttribute(gather_kernel,
                             cudaFuncAttributeMaxDynamicSharedMemorySize, SMEM_MAIN);
        smem_set = 1;
    }

    // Phase 1: repack P -> P2h (fp16, o contiguous)
    {
        dim3 grid(IJ / 32, NOUT / 32, NC * NC);
        dim3 block(32, 8);
        repack_kernel<<<grid, block>>>(P);
    }
    // Phase 2: cell-major gather, 148 persistent blocks
    {
        gather_kernel<<<NBLK, 512, SMEM_MAIN>>>(x, z, borders, invlen);
    }
    // Phase 3: reduce 148 partials
    {
        reduce_kernel<<<OUTE / 256, 256>>>(out);
    }
}

// round 8
// speedup vs baseline: 1.3921x; 1.3921x over previous
#include <cuda_runtime.h>
#include <cuda_fp16.h>
#include <math.h>

// Problem constants
#define NG   16          // NUM_GRIDS
#define NIX  32          // IN_X
#define NIZ  32          // IN_Z
#define NOUT 64          // OUT
#define NB   512         // BATCH
#define NC   17          // NUM_GRIDS + 1
#define IJ   (NIX * NIZ)         // 1024
#define JSTRH (IJ * NOUT)        // 65536 halfs: jj -> jj+1 step in P2h
#define ISTRH (NC * JSTRH)       // ii -> ii+1 step in P2h

// Repacked parameter tensor in fp16: P2h[cell][ij][o]  (o contiguous)
__device__ __half g_P2h[NC * NC * IJ * NOUT];

// ---------------------------------------------------------------------------
// Repack v2: P[cell][o][ij] (fp32) -> P2h[cell][ij][o] (fp16).
// Tile 64 o x 32 ij. Vectorized: float4 loads, uint4 (8-half) stores.
// smem pitch 33 floats -> store-side column LDS is 2-way-conflict only.
// ~3.6 instr/elem vs 7.5 in the scalar version (repack was issue-bound,
// alu=38.5% / issue=50.9% / DRAM=48%).
// ---------------------------------------------------------------------------
__global__ __launch_bounds__(256) void repack_kernel(const float* __restrict__ P) {
    __shared__ float tile[NOUT * 33];         // 8448 B
    const int cell = blockIdx.x >> 5;         // 0..288
    const int ij0  = (blockIdx.x & 31) << 5;  // 0..992
    const int t    = threadIdx.x;

    const float* src = P     + cell * (NOUT * IJ) + ij0;
    __half*      dst = g_P2h + cell * (IJ * NOUT) + ij0 * NOUT;

    // Load: 512 float4 (64 o-rows x 8 float4 of 32 ij) -> 2 per thread.
#pragma unroll
    for (int p = 0; p < 2; ++p) {
        const int f = t + p * 256;
        const int o = f >> 3;                 // 0..63
        const int c = f & 7;                  // 0..7
        const float4 v = *reinterpret_cast<const float4*>(src + o * IJ + c * 4);
        float* tp = tile + o * 33 + c * 4;
        tp[0] = v.x; tp[1] = v.y; tp[2] = v.z; tp[3] = v.w;
    }
    __syncthreads();

    // Store: 256 uint4 (32 ij x 8 o-groups) -> 1 per thread.
    // og fastest across lanes -> 8 lanes cover one contiguous 128B o-row.
    const int ij = t >> 3;                    // 0..31
    const int og = t & 7;                     // 0..7
    float v[8];
#pragma unroll
    for (int m = 0; m < 8; ++m)
        v[m] = tile[(og * 8 + m) * 33 + ij];
    __half2 h0 = __floats2half2_rn(v[0], v[1]);
    __half2 h1 = __floats2half2_rn(v[2], v[3]);
    __half2 h2 = __floats2half2_rn(v[4], v[5]);
    __half2 h3 = __floats2half2_rn(v[6], v[7]);
    uint4 q;
    q.x = *reinterpret_cast<unsigned*>(&h0);
    q.y = *reinterpret_cast<unsigned*>(&h1);
    q.z = *reinterpret_cast<unsigned*>(&h2);
    q.w = *reinterpret_cast<unsigned*>(&h3);
    *reinterpret_cast<uint4*>(dst + ij * NOUT + og * 8) = q;
}

// ---------------------------------------------------------------------------
// fp16x8 weighted accumulate: acc[0..7] += w * (8 halfs in q)
// ---------------------------------------------------------------------------
__device__ __forceinline__ void accum8(float acc[8], uint4 q, float w) {
    const __half2* h = reinterpret_cast<const __half2*>(&q);
#pragma unroll
    for (int m = 0; m < 4; ++m) {
        const float2 f = __half22float2(h[m]);
        acc[2 * m + 0] += w * f.x;
        acc[2 * m + 1] += w * f.y;
    }
}

// ---------------------------------------------------------------------------
// Gather (round-5 proven, 25.0us): grid (NB), block 512, one batch per block;
// all blocks sweep the same ij order (cross-batch L2 reuse). 8 lanes x 8
// halfs cover the full 64-o row (128B lines). At ~87% of the NAT LTS cap --
// structural wall for batch-major.
// ---------------------------------------------------------------------------
__global__ __launch_bounds__(512) void gather_kernel(
    const float* __restrict__ x,
    const float* __restrict__ z,
    const float* __restrict__ borders,
    const float* __restrict__ invlen,
    float* __restrict__ out)
{
    const int b   = blockIdx.x;
    const int tid = threadIdx.x;

    __shared__ int   s_ix[NIX];
    __shared__ int   s_iz[NIZ];
    __shared__ float s_dx[NIX];
    __shared__ float s_dz[NIZ];

    // Per-batch index/weight precompute (laplace cdf binning)
    if (tid < 64) {
        const float v = (tid < 32) ? x[tid * NB + b] : z[(tid - 32) * NB + b];
        const float e = expf(-fabsf(v));
        const float cdf = (v > 0.0f) ? (1.0f - 0.5f * e) : (0.5f * e);
        int idx = (int)(cdf * (float)NG);
        idx = max(0, min(NG - 1, idx));
        const float d = (v - borders[idx]) * invlen[idx];
        if (tid < 32) { s_ix[tid] = idx;      s_dx[tid] = d; }
        else          { s_iz[tid - 32] = idx; s_dz[tid - 32] = d; }
    }
    __syncthreads();

    const int og  = tid & 7;        // o-group: halfs [og*8, og*8+8) of 64
    const int ijg = tid >> 3;       // ij-group 0..63
    const int ooff = og * 8;

    float acc[8];
#pragma unroll
    for (int e = 0; e < 8; ++e) acc[e] = 0.0f;

#pragma unroll 4
    for (int k = 0; k < IJ / 64; ++k) {     // 16 sweep steps
        const int ij = ijg + (k << 6);
        const int i = ij >> 5;
        const int j = ij & 31;
        const int   ix = s_ix[i];
        const int   iz = s_iz[j];
        const float dx = s_dx[i];
        const float dz = s_dz[j];
        const float ax = 1.0f - dx;
        const float az = 1.0f - dz;
        const float w00 = ax * az;
        const float w01 = ax * dz;
        const float w10 = dx * az;
        const float w11 = dx * dz;

        const int base = ((ix * NC + iz) * IJ + ij) * NOUT + ooff;  // half units
        const __half* p = g_P2h + base;

        const uint4 q00 = *reinterpret_cast<const uint4*>(p);
        const uint4 q01 = *reinterpret_cast<const uint4*>(p + JSTRH);
        const uint4 q10 = *reinterpret_cast<const uint4*>(p + ISTRH);
        const uint4 q11 = *reinterpret_cast<const uint4*>(p + ISTRH + JSTRH);

        accum8(acc, q00, w00);
        accum8(acc, q01, w01);
        accum8(acc, q10, w10);
        accum8(acc, q11, w11);
    }

    // Warp reduction over the 4 ij-groups per warp (lane = (ijg&3)*8 + og)
#pragma unroll
    for (int m = 8; m <= 16; m <<= 1)
#pragma unroll
        for (int e = 0; e < 8; ++e)
            acc[e] += __shfl_xor_sync(0xffffffffu, acc[e], m);

    // Cross-warp reduction: 16 warps x 8 o-groups x 8 elems
    __shared__ float s_part[16][8][8];
    const int warp = tid >> 5;
    const int lane = tid & 31;
    if (lane < 8) {
#pragma unroll
        for (int e = 0; e < 8; ++e) s_part[warp][lane][e] = acc[e];
    }
    __syncthreads();

    if (tid < 64) {
        const int og2 = tid >> 3;       // o-group
        const int e   = tid & 7;        // element within group
        float a = s_part[0][og2][e];
#pragma unroll
        for (int w = 1; w < 16; ++w) a += s_part[w][og2][e];
        out[(og2 * 8 + e) * NB + b] = a;
    }
}

// ---------------------------------------------------------------------------
extern "C" void kernel_launch(void* const* d_in, const int* in_sizes, int n_in,
                              void* d_out, int out_size) {
    const float* x       = (const float*)d_in[0];  // (32, 512)
    const float* z       = (const float*)d_in[1];  // (32, 512)
    const float* P       = (const float*)d_in[2];  // (17,17,64,32,32)
    const float* borders = (const float*)d_in[3];  // (17,)
    const float* invlen  = (const float*)d_in[4];  // (16,)
    float* out = (float*)d_out;                    // (64, 512)

    (void)in_sizes; (void)n_in; (void)out_size;

    // Phase 1: repack P -> P2h (fp16, o contiguous), vectorized
    {
        repack_kernel<<<NC * NC * 32, 256>>>(P);   // 9248 blocks
    }

    // Phase 2: gather + accumulate (round-5 proven config)
    {
        gather_kernel<<<NB, 512>>>(x, z, borders, invlen, out);
    }
}